// round 8
// baseline (speedup 1.0000x reference)
#include <cuda_runtime.h>
#include <cuda_fp16.h>
#include <cstdint>

// ---------------------------------------------------------------------------
// Seq2SeqForecast: 2-layer GRU encoder (B=512, T=336, H=512) + 48-step GRU
// decoder with scalar head.
//
// Strategy:
//  * All big per-step GEMMs (M=512, N=1536, K=512) run on tensor cores via
//    mma.sync.m16n8k16 (fp16 inputs, fp32 accum). Weights converted to fp16
//    once per launch; h kept in fp32 (for the z*h blend) + fp16 shadow (MMA A).
//  * Encoder layers fused into ONE kernel per time step with a 1-step lag:
//    kernel t computes h0[t] (layer0) and h1[t-1] (layer1) concurrently.
//  * Ping-pong parity buffers; ~440 total graph nodes.
// ---------------------------------------------------------------------------

#define HDIM   512
#define BATCH  512
#define TSTEPS 336
#define HORIZON 48
#define G3H    (3 * HDIM)          // 1536

// fp16 weight copies
__device__ __half g_Whh0[G3H * HDIM];
__device__ __half g_Wih1[G3H * HDIM];
__device__ __half g_Whh1[G3H * HDIM];
__device__ __half g_cWhh[G3H * HDIM];

// hidden-state ping-pong buffers (fp32 master + fp16 shadow for MMA)
__device__ float  g_h0_f32[2][BATCH * HDIM];
__device__ __half g_h0_f16[2][BATCH * HDIM];
__device__ float  g_h1_f32[2][BATCH * HDIM];
__device__ __half g_h1_f16[2][BATCH * HDIM];
__device__ float  g_hd_f32[2][BATCH * HDIM];
__device__ __half g_hd_f16[2][BATCH * HDIM];
__device__ float  g_lastv[BATCH];

// ---------------------------------------------------------------------------
// helpers
// ---------------------------------------------------------------------------
__device__ __forceinline__ void mma16816(float (&c)[4], const uint32_t (&a)[4],
                                         uint32_t b0, uint32_t b1) {
    asm volatile(
        "mma.sync.aligned.m16n8k16.row.col.f32.f16.f16.f32 "
        "{%0,%1,%2,%3}, {%4,%5,%6,%7}, {%8,%9}, {%0,%1,%2,%3};\n"
        : "+f"(c[0]), "+f"(c[1]), "+f"(c[2]), "+f"(c[3])
        : "r"(a[0]), "r"(a[1]), "r"(a[2]), "r"(a[3]), "r"(b0), "r"(b1));
}

__device__ __forceinline__ float sigmoidf_(float x) {
    return 1.0f / (1.0f + expf(-x));
}

// ---------------------------------------------------------------------------
// Core GRU tile: block computes a 64(batch) x 32(hidden) tile of h_new.
// gh = h_prev @ Wghᵀ (+bhh) always via MMA.
// gi either via MMA (HAS_GI: layer1) or inline small dot (IN_FEAT = 8 or 9).
// smem layout (halves, stride 72/row): As0[64] Bs0[96] As1[64] Bs1[96]
// ---------------------------------------------------------------------------
template <bool HAS_GI, int IN_FEAT, bool HAS_XFIRST>
__device__ __forceinline__ void gru_block(
    __half* __restrict__ smem, int m0, int n0,
    const __half* __restrict__ Agh, const __half* __restrict__ Wgh,
    const __half* __restrict__ Agi, const __half* __restrict__ Wgi,
    const float* __restrict__ bih, const float* __restrict__ bhh,
    const float* __restrict__ WihS,  // [1536 x IN_FEAT] small input weights
    const float* __restrict__ xrow, int xstride,
    const float* __restrict__ xfirst,
    const float* __restrict__ hprev, float* __restrict__ hout,
    __half* __restrict__ hout16) {

    const int tid  = threadIdx.x;
    const int lane = tid & 31;
    const int wid  = tid >> 5;       // 8 warps
    const int wm   = wid >> 1;       // 4 warps along M
    const int wn   = wid & 1;        // 2 warps along N
    const int g4   = lane >> 2;      // 0..7
    const int t4   = lane & 3;       // 0..3

    __half* As0 = smem;              // 64 x 72
    __half* Bs0 = smem + 64 * 72;    // 96 x 72
    __half* As1 = smem + 160 * 72;   // 64 x 72
    __half* Bs1 = smem + 224 * 72;   // 96 x 72

    float acc_gh[3][2][4];
    float acc_gi[3][2][4];
#pragma unroll
    for (int g = 0; g < 3; g++)
#pragma unroll
        for (int nh = 0; nh < 2; nh++)
#pragma unroll
            for (int i = 0; i < 4; i++) {
                acc_gh[g][nh][i] = 0.f;
                if (HAS_GI) acc_gi[g][nh][i] = 0.f;
            }

    const int arow0 = (wm * 16 + g4) * 72;
    const int arow1 = arow0 + 8 * 72;

    for (int k0 = 0; k0 < HDIM; k0 += 64) {
        // stage A tiles (64 rows x 64 k halves), 8 uint4/row
#pragma unroll
        for (int i = 0; i < 2; i++) {
            int idx = tid + i * 256;
            int r = idx >> 3, c = idx & 7;
            *(uint4*)(As0 + r * 72 + c * 8) =
                *(const uint4*)(Agh + (m0 + r) * HDIM + k0 + c * 8);
            if (HAS_GI)
                *(uint4*)(As1 + r * 72 + c * 8) =
                    *(const uint4*)(Agi + (m0 + r) * HDIM + k0 + c * 8);
        }
        // stage B tiles (3 gates x 32 n-rows) x 64 k
#pragma unroll
        for (int i = 0; i < 3; i++) {
            int idx = tid + i * 256;
            int r = idx >> 3, c = idx & 7;                   // r in 0..95
            int grow = (r >> 5) * HDIM + n0 + (r & 31);      // gate*512 + n
            *(uint4*)(Bs0 + r * 72 + c * 8) =
                *(const uint4*)(Wgh + grow * HDIM + k0 + c * 8);
            if (HAS_GI)
                *(uint4*)(Bs1 + r * 72 + c * 8) =
                    *(const uint4*)(Wgi + grow * HDIM + k0 + c * 8);
        }
        __syncthreads();

#pragma unroll
        for (int kk = 0; kk < 64; kk += 16) {
            const int kc = kk + t4 * 2;
            uint32_t a0[4], a1[4];
            a0[0] = *(const uint32_t*)(As0 + arow0 + kc);
            a0[1] = *(const uint32_t*)(As0 + arow1 + kc);
            a0[2] = *(const uint32_t*)(As0 + arow0 + kc + 8);
            a0[3] = *(const uint32_t*)(As0 + arow1 + kc + 8);
            if (HAS_GI) {
                a1[0] = *(const uint32_t*)(As1 + arow0 + kc);
                a1[1] = *(const uint32_t*)(As1 + arow1 + kc);
                a1[2] = *(const uint32_t*)(As1 + arow0 + kc + 8);
                a1[3] = *(const uint32_t*)(As1 + arow1 + kc + 8);
            }
#pragma unroll
            for (int g = 0; g < 3; g++) {
#pragma unroll
                for (int nh = 0; nh < 2; nh++) {
                    int brow = (g * 32 + wn * 16 + nh * 8 + g4) * 72 + kc;
                    uint32_t b0 = *(const uint32_t*)(Bs0 + brow);
                    uint32_t b1 = *(const uint32_t*)(Bs0 + brow + 8);
                    mma16816(acc_gh[g][nh], a0, b0, b1);
                    if (HAS_GI) {
                        uint32_t c0 = *(const uint32_t*)(Bs1 + brow);
                        uint32_t c1 = *(const uint32_t*)(Bs1 + brow + 8);
                        mma16816(acc_gi[g][nh], a1, c0, c1);
                    }
                }
            }
        }
        __syncthreads();
    }

    // ---- epilogue: gates fully in registers (known mma C layout) ----
    const int mbase = m0 + wm * 16 + g4;
    const int nbase = n0 + wn * 16 + t4 * 2;

#pragma unroll
    for (int hm = 0; hm < 2; hm++) {
        const int row = mbase + hm * 8;
        float xv[IN_FEAT > 0 ? IN_FEAT : 1];
        if constexpr (!HAS_GI) {
            if constexpr (HAS_XFIRST) {
                xv[0] = xfirst[row];
#pragma unroll
                for (int i = 1; i < IN_FEAT; i++)
                    xv[i] = xrow[row * xstride + i - 1];
            } else {
#pragma unroll
                for (int i = 0; i < IN_FEAT; i++)
                    xv[i] = xrow[row * xstride + i];
            }
        }
#pragma unroll
        for (int nh = 0; nh < 2; nh++) {
            const int j0 = nbase + nh * 8;
            float2 hp = *(const float2*)(hprev + row * HDIM + j0);
            float2 ho;
#pragma unroll
            for (int cc = 0; cc < 2; cc++) {
                const int j = j0 + cc;
                const int ci = hm * 2 + cc;
                float gir, giz, gin;
                if constexpr (HAS_GI) {
                    gir = acc_gi[0][nh][ci] + bih[j];
                    giz = acc_gi[1][nh][ci] + bih[HDIM + j];
                    gin = acc_gi[2][nh][ci] + bih[2 * HDIM + j];
                } else {
                    gir = bih[j];
                    giz = bih[HDIM + j];
                    gin = bih[2 * HDIM + j];
                    const float* wr = WihS + j * IN_FEAT;
                    const float* wz = WihS + (HDIM + j) * IN_FEAT;
                    const float* wn_ = WihS + (2 * HDIM + j) * IN_FEAT;
#pragma unroll
                    for (int i = 0; i < IN_FEAT; i++) {
                        gir += xv[i] * wr[i];
                        giz += xv[i] * wz[i];
                        gin += xv[i] * wn_[i];
                    }
                }
                float ghr = acc_gh[0][nh][ci] + bhh[j];
                float ghz = acc_gh[1][nh][ci] + bhh[HDIM + j];
                float ghn = acc_gh[2][nh][ci] + bhh[2 * HDIM + j];
                float rg = sigmoidf_(gir + ghr);
                float zg = sigmoidf_(giz + ghz);
                float ng = tanhf(gin + rg * ghn);
                float hpv = cc ? hp.y : hp.x;
                float hv = (1.0f - zg) * ng + zg * hpv;
                if (cc) ho.y = hv; else ho.x = hv;
            }
            *(float2*)(hout + row * HDIM + j0) = ho;
            __half2 h2;
            h2.x = __float2half(ho.x);
            h2.y = __float2half(ho.y);
            *(__half2*)(hout16 + row * HDIM + j0) = h2;
        }
    }
}

// ---------------------------------------------------------------------------
// Fused encoder step: blocks [0,128) -> layer0 h0[t]; [128,256) -> layer1
// h1[t-1] (one-step lag makes the two halves independent).
// ---------------------------------------------------------------------------
__global__ __launch_bounds__(256)
void enc_step_kernel(int t, const float* __restrict__ src,
                     const float* __restrict__ bih0, const float* __restrict__ bhh0,
                     const float* __restrict__ Wih0,
                     const float* __restrict__ bih1, const float* __restrict__ bhh1) {
    __shared__ __align__(16) __half smem[320 * 72];
    const int role = (blockIdx.x < 128) ? 0 : 1;
    const int bid = blockIdx.x & 127;
    const int m0 = (bid >> 4) * 64;
    const int n0 = (bid & 15) * 32;

    if (role == 0) {
        if (t >= TSTEPS) return;
        const int pw = t & 1, pr = (t + 1) & 1;   // h0[t-1] at parity (t-1)&1
        gru_block<false, 8, false>(smem, m0, n0,
            g_h0_f16[pr], g_Whh0, nullptr, nullptr,
            bih0, bhh0, Wih0, src + t * 8, TSTEPS * 8, nullptr,
            g_h0_f32[pr], g_h0_f32[pw], g_h0_f16[pw]);
    } else {
        if (t < 1) return;
        const int tt = t - 1;                     // computing h1[tt]
        const int pw = tt & 1, pr = (tt + 1) & 1; // h1[tt-1] parity
        gru_block<true, 0, false>(smem, m0, n0,
            g_h1_f16[pr], g_Whh1, g_h0_f16[tt & 1], g_Wih1,
            bih1, bhh1, nullptr, nullptr, 0, nullptr,
            g_h1_f32[pr], g_h1_f32[pw], g_h1_f16[pw]);
    }
}

// ---------------------------------------------------------------------------
// Decoder GRU cell step (gi inline from [last_value, tf_t], 9 features)
// ---------------------------------------------------------------------------
__global__ __launch_bounds__(256)
void dec_step_kernel(int s, const float* __restrict__ tf,
                     const float* __restrict__ cbih, const float* __restrict__ cbhh,
                     const float* __restrict__ cWih) {
    __shared__ __align__(16) __half smem[320 * 72];
    const int bid = blockIdx.x;
    const int m0 = (bid >> 4) * 64;
    const int n0 = (bid & 15) * 32;
    const int pr = s & 1, pw = (s + 1) & 1;
    gru_block<false, 9, true>(smem, m0, n0,
        g_hd_f16[pr], g_cWhh, nullptr, nullptr,
        cbih, cbhh, cWih, tf + s * 8, HORIZON * 8, g_lastv,
        g_hd_f32[pr], g_hd_f32[pw], g_hd_f16[pw]);
}

// ---------------------------------------------------------------------------
// fc head: pred[b] = hidden[b] . fc_W + fc_b ; also feeds next last_value
// ---------------------------------------------------------------------------
__global__ __launch_bounds__(256)
void fc_kernel(int s, const float* __restrict__ fcW, const float* __restrict__ fcb,
               float* __restrict__ out) {
    const int b = blockIdx.x * 8 + (threadIdx.x >> 5);
    const int lane = threadIdx.x & 31;
    const float* h = g_hd_f32[(s + 1) & 1] + b * HDIM;
    float sum = 0.f;
#pragma unroll
    for (int k = lane; k < HDIM; k += 32) sum += h[k] * fcW[k];
#pragma unroll
    for (int o = 16; o; o >>= 1) sum += __shfl_xor_sync(0xffffffffu, sum, o);
    if (lane == 0) {
        float p = sum + fcb[0];
        out[b * HORIZON + s] = p;
        g_lastv[b] = p;
    }
}

// ---------------------------------------------------------------------------
// dec0 linear: hidden0 = h1[T-1] @ dec0_Wᵀ + dec0_b  (one-time, fp32 SIMT)
// ---------------------------------------------------------------------------
__global__ __launch_bounds__(256)
void dec0_kernel(const float* __restrict__ W, const float* __restrict__ bias) {
    __shared__ float As[64][17];
    __shared__ float Ws[64][17];
    const float* A = g_h1_f32[(TSTEPS - 1) & 1];
    const int m0 = blockIdx.y * 64, n0 = blockIdx.x * 64;
    const int tx = threadIdx.x & 15, ty = threadIdx.x >> 4;
    float acc[4][4] = {};
    for (int k0 = 0; k0 < HDIM; k0 += 16) {
#pragma unroll
        for (int i = 0; i < 4; i++) {
            int idx = threadIdx.x + i * 256;
            int r = idx >> 4, c = idx & 15;
            As[r][c] = A[(m0 + r) * HDIM + k0 + c];
            Ws[r][c] = W[(n0 + r) * HDIM + k0 + c];
        }
        __syncthreads();
#pragma unroll
        for (int kk = 0; kk < 16; kk++) {
            float a[4], w[4];
#pragma unroll
            for (int i = 0; i < 4; i++) { a[i] = As[ty * 4 + i][kk]; w[i] = Ws[tx * 4 + i][kk]; }
#pragma unroll
            for (int i = 0; i < 4; i++)
#pragma unroll
                for (int j = 0; j < 4; j++) acc[i][j] += a[i] * w[j];
        }
        __syncthreads();
    }
#pragma unroll
    for (int i = 0; i < 4; i++)
#pragma unroll
        for (int j = 0; j < 4; j++) {
            int m = m0 + ty * 4 + i, n = n0 + tx * 4 + j;
            float v = acc[i][j] + bias[n];
            g_hd_f32[0][m * HDIM + n] = v;
            g_hd_f16[0][m * HDIM + n] = __float2half(v);
        }
}

// ---------------------------------------------------------------------------
// setup kernels
// ---------------------------------------------------------------------------
__global__ void convert_weights_kernel(const float* __restrict__ Whh0,
                                       const float* __restrict__ Wih1,
                                       const float* __restrict__ Whh1,
                                       const float* __restrict__ cWhh) {
    int i = blockIdx.x * blockDim.x + threadIdx.x;
    if (i < G3H * HDIM) {
        g_Whh0[i] = __float2half(Whh0[i]);
        g_Wih1[i] = __float2half(Wih1[i]);
        g_Whh1[i] = __float2half(Whh1[i]);
        g_cWhh[i] = __float2half(cWhh[i]);
    }
}

__global__ void init_kernel(const float* __restrict__ src) {
    int i = blockIdx.x * blockDim.x + threadIdx.x;
    if (i < BATCH * HDIM) {
        g_h0_f32[1][i] = 0.f;
        g_h1_f32[1][i] = 0.f;
        g_h0_f16[1][i] = __float2half(0.f);
        g_h1_f16[1][i] = __float2half(0.f);
    }
    if (i < BATCH) g_lastv[i] = src[i * (TSTEPS * 8) + (TSTEPS - 1) * 8];
}

// ---------------------------------------------------------------------------
extern "C" void kernel_launch(void* const* d_in, const int* in_sizes, int n_in,
                              void* d_out, int out_size) {
    const float* src   = (const float*)d_in[0];
    const float* tf    = (const float*)d_in[1];
    const float* Wih0  = (const float*)d_in[2];
    const float* Whh0  = (const float*)d_in[3];
    const float* bih0  = (const float*)d_in[4];
    const float* bhh0  = (const float*)d_in[5];
    // Wih1 = d_in[6] (used via fp16 copy)
    const float* Wih1  = (const float*)d_in[6];
    const float* Whh1  = (const float*)d_in[7];
    const float* bih1  = (const float*)d_in[8];
    const float* bhh1  = (const float*)d_in[9];
    const float* dec0W = (const float*)d_in[10];
    const float* dec0b = (const float*)d_in[11];
    const float* cWih  = (const float*)d_in[12];
    const float* cWhh  = (const float*)d_in[13];
    const float* cbih  = (const float*)d_in[14];
    const float* cbhh  = (const float*)d_in[15];
    const float* fcW   = (const float*)d_in[16];
    const float* fcb   = (const float*)d_in[17];
    float* out = (float*)d_out;

    convert_weights_kernel<<<(G3H * HDIM + 255) / 256, 256>>>(Whh0, Wih1, Whh1, cWhh);
    init_kernel<<<(BATCH * HDIM + 255) / 256, 256>>>(src);

    // Encoder: T+1 fused launches (layer1 lags layer0 by one step)
    for (int t = 0; t <= TSTEPS; t++)
        enc_step_kernel<<<256, 256>>>(t, src, bih0, bhh0, Wih0, bih1, bhh1);

    // Decoder init + 48 steps
    dec0_kernel<<<dim3(8, 8), 256>>>(dec0W, dec0b);
    for (int s = 0; s < HORIZON; s++) {
        dec_step_kernel<<<128, 256>>>(s, tf, cbih, cbhh, cWih);
        fc_kernel<<<64, 256>>>(s, fcW, fcb, out);
    }
}

// round 9
// speedup vs baseline: 1.2343x; 1.2343x over previous
#include <cuda_runtime.h>
#include <cuda_fp16.h>
#include <cstdint>

// ---------------------------------------------------------------------------
// Seq2SeqForecast: 2-layer GRU encoder (B=512, T=336, H=512) + 48-step GRU
// decoder with scalar head.
//
// R8 changes vs R5 baseline (8994us, enc_step 31.9us, occ 12.6%):
//  * __launch_bounds__(256, 2): 2 CTAs/SM (was reg-limited to 1) -> single
//    wave for all 256 encoder blocks, 16 warps/SM.
//  * cp.async.cg double-buffered smem pipeline: stage chunk k+1 while
//    running MMAs on chunk k; staging no longer burns registers.
//  * Dynamic smem (92KB enc / 46KB dec) via cudaFuncSetAttribute.
// ---------------------------------------------------------------------------

#define HDIM   512
#define BATCH  512
#define TSTEPS 336
#define HORIZON 48
#define G3H    (3 * HDIM)          // 1536

// fp16 weight copies
__device__ __half g_Whh0[G3H * HDIM];
__device__ __half g_Wih1[G3H * HDIM];
__device__ __half g_Whh1[G3H * HDIM];
__device__ __half g_cWhh[G3H * HDIM];

// hidden-state ping-pong buffers (fp32 master + fp16 shadow for MMA)
__device__ float  g_h0_f32[2][BATCH * HDIM];
__device__ __half g_h0_f16[2][BATCH * HDIM];
__device__ float  g_h1_f32[2][BATCH * HDIM];
__device__ __half g_h1_f16[2][BATCH * HDIM];
__device__ float  g_hd_f32[2][BATCH * HDIM];
__device__ __half g_hd_f16[2][BATCH * HDIM];
__device__ float  g_lastv[BATCH];

// ---------------------------------------------------------------------------
// helpers
// ---------------------------------------------------------------------------
__device__ __forceinline__ void mma16816(float (&c)[4], const uint32_t (&a)[4],
                                         uint32_t b0, uint32_t b1) {
    asm volatile(
        "mma.sync.aligned.m16n8k16.row.col.f32.f16.f16.f32 "
        "{%0,%1,%2,%3}, {%4,%5,%6,%7}, {%8,%9}, {%0,%1,%2,%3};\n"
        : "+f"(c[0]), "+f"(c[1]), "+f"(c[2]), "+f"(c[3])
        : "r"(a[0]), "r"(a[1]), "r"(a[2]), "r"(a[3]), "r"(b0), "r"(b1));
}

__device__ __forceinline__ float sigmoidf_(float x) {
    return 1.0f / (1.0f + expf(-x));
}

__device__ __forceinline__ void cp16(uint32_t dst, const void* src) {
    asm volatile("cp.async.cg.shared.global [%0], [%1], 16;\n"
                 :: "r"(dst), "l"(src));
}
__device__ __forceinline__ void cp_commit() {
    asm volatile("cp.async.commit_group;\n");
}
template <int N>
__device__ __forceinline__ void cp_wait() {
    asm volatile("cp.async.wait_group %0;\n" :: "n"(N));
}

// ---------------------------------------------------------------------------
// Core GRU tile: block computes a 64(batch) x 32(hidden) tile of h_new.
// gh = h_prev @ Wghᵀ (+bhh) always via MMA.
// gi either via MMA (HAS_GI: layer1) or inline small dot (IN_FEAT = 8 or 9).
// Double-buffered smem (stride BSTRIDE halves per buffer); per-buffer layout
// (row stride 72 halves): As0[64] Bs0[96] [As1[64] Bs1[96] if HAS_GI].
// ---------------------------------------------------------------------------
template <bool HAS_GI, int IN_FEAT, bool HAS_XFIRST, int BSTRIDE>
__device__ __forceinline__ void gru_block(
    __half* __restrict__ smem, int m0, int n0,
    const __half* __restrict__ Agh, const __half* __restrict__ Wgh,
    const __half* __restrict__ Agi, const __half* __restrict__ Wgi,
    const float* __restrict__ bih, const float* __restrict__ bhh,
    const float* __restrict__ WihS,  // [1536 x IN_FEAT] small input weights
    const float* __restrict__ xrow, int xstride,
    const float* __restrict__ xfirst,
    const float* __restrict__ hprev, float* __restrict__ hout,
    __half* __restrict__ hout16) {

    const int tid  = threadIdx.x;
    const int lane = tid & 31;
    const int wid  = tid >> 5;       // 8 warps
    const int wm   = wid >> 1;       // 4 warps along M
    const int wn   = wid & 1;        // 2 warps along N
    const int g4   = lane >> 2;      // 0..7
    const int t4   = lane & 3;       // 0..3

    // ---- cp.async staging setup ----
    const int r8 = tid >> 3;         // 0..31
    const int c8 = tid & 7;          // 0..7 (uint4 within 64-half k-chunk)
    uint32_t sbase = (uint32_t)__cvta_generic_to_shared(smem);
    const uint32_t sA  = sbase + (uint32_t)((r8 * 72 + c8 * 8) * 2);
    const uint32_t sB  = sbase + (uint32_t)((64 * 72 + r8 * 72 + c8 * 8) * 2);
    const __half* pA0   = Agh + (m0 + r8) * HDIM + c8 * 8;
    const __half* pB0_0 = Wgh + (0 * HDIM + n0 + r8) * HDIM + c8 * 8;
    const __half* pB0_1 = Wgh + (1 * HDIM + n0 + r8) * HDIM + c8 * 8;
    const __half* pB0_2 = Wgh + (2 * HDIM + n0 + r8) * HDIM + c8 * 8;
    const __half* pA1   = HAS_GI ? Agi + (m0 + r8) * HDIM + c8 * 8 : nullptr;
    const __half* pB1_0 = HAS_GI ? Wgi + (0 * HDIM + n0 + r8) * HDIM + c8 * 8 : nullptr;
    const __half* pB1_1 = HAS_GI ? Wgi + (1 * HDIM + n0 + r8) * HDIM + c8 * 8 : nullptr;
    const __half* pB1_2 = HAS_GI ? Wgi + (2 * HDIM + n0 + r8) * HDIM + c8 * 8 : nullptr;

    auto stage = [&](int ks) {
        const uint32_t bo = (uint32_t)((ks & 1) * BSTRIDE * 2);
        const int ko = ks * 64;
        cp16(sA + bo, pA0 + ko);
        cp16(sA + bo + 32 * 72 * 2, pA0 + 32 * HDIM + ko);
        cp16(sB + bo, pB0_0 + ko);
        cp16(sB + bo + 32 * 72 * 2, pB0_1 + ko);
        cp16(sB + bo + 64 * 72 * 2, pB0_2 + ko);
        if (HAS_GI) {
            const uint32_t bo1 = bo + 160 * 72 * 2;
            cp16(sA + bo1, pA1 + ko);
            cp16(sA + bo1 + 32 * 72 * 2, pA1 + 32 * HDIM + ko);
            const uint32_t bo2 = bo + 160 * 72 * 2;
            cp16(sB + bo2, pB1_0 + ko);
            cp16(sB + bo2 + 32 * 72 * 2, pB1_1 + ko);
            cp16(sB + bo2 + 64 * 72 * 2, pB1_2 + ko);
        }
        cp_commit();
    };

    float acc_gh[3][2][4];
    float acc_gi[3][2][4];
#pragma unroll
    for (int g = 0; g < 3; g++)
#pragma unroll
        for (int nh = 0; nh < 2; nh++)
#pragma unroll
            for (int i = 0; i < 4; i++) {
                acc_gh[g][nh][i] = 0.f;
                if (HAS_GI) acc_gi[g][nh][i] = 0.f;
            }

    const int arow0 = (wm * 16 + g4) * 72;
    const int arow1 = arow0 + 8 * 72;

    stage(0);

    for (int ks = 0; ks < 8; ks++) {
        if (ks < 7) { stage(ks + 1); cp_wait<1>(); }
        else        { cp_wait<0>(); }
        __syncthreads();

        const __half* buf = smem + (ks & 1) * BSTRIDE;
        const __half* As0 = buf;
        const __half* Bs0 = buf + 64 * 72;
        const __half* As1 = buf + 160 * 72;
        const __half* Bs1 = buf + 224 * 72;

#pragma unroll
        for (int kk = 0; kk < 64; kk += 16) {
            const int kc = kk + t4 * 2;
            uint32_t a0[4], a1[4];
            a0[0] = *(const uint32_t*)(As0 + arow0 + kc);
            a0[1] = *(const uint32_t*)(As0 + arow1 + kc);
            a0[2] = *(const uint32_t*)(As0 + arow0 + kc + 8);
            a0[3] = *(const uint32_t*)(As0 + arow1 + kc + 8);
            if (HAS_GI) {
                a1[0] = *(const uint32_t*)(As1 + arow0 + kc);
                a1[1] = *(const uint32_t*)(As1 + arow1 + kc);
                a1[2] = *(const uint32_t*)(As1 + arow0 + kc + 8);
                a1[3] = *(const uint32_t*)(As1 + arow1 + kc + 8);
            }
#pragma unroll
            for (int g = 0; g < 3; g++) {
#pragma unroll
                for (int nh = 0; nh < 2; nh++) {
                    int brow = (g * 32 + wn * 16 + nh * 8 + g4) * 72 + kc;
                    uint32_t b0 = *(const uint32_t*)(Bs0 + brow);
                    uint32_t b1 = *(const uint32_t*)(Bs0 + brow + 8);
                    mma16816(acc_gh[g][nh], a0, b0, b1);
                    if (HAS_GI) {
                        uint32_t c0 = *(const uint32_t*)(Bs1 + brow);
                        uint32_t c1 = *(const uint32_t*)(Bs1 + brow + 8);
                        mma16816(acc_gi[g][nh], a1, c0, c1);
                    }
                }
            }
        }
        __syncthreads();
    }

    // ---- epilogue: gates fully in registers (known mma C layout) ----
    const int mbase = m0 + wm * 16 + g4;
    const int nbase = n0 + wn * 16 + t4 * 2;

#pragma unroll
    for (int hm = 0; hm < 2; hm++) {
        const int row = mbase + hm * 8;
        float xv[IN_FEAT > 0 ? IN_FEAT : 1];
        if constexpr (!HAS_GI) {
            if constexpr (HAS_XFIRST) {
                xv[0] = xfirst[row];
#pragma unroll
                for (int i = 1; i < IN_FEAT; i++)
                    xv[i] = xrow[row * xstride + i - 1];
            } else {
#pragma unroll
                for (int i = 0; i < IN_FEAT; i++)
                    xv[i] = xrow[row * xstride + i];
            }
        }
#pragma unroll
        for (int nh = 0; nh < 2; nh++) {
            const int j0 = nbase + nh * 8;
            float2 hp = *(const float2*)(hprev + row * HDIM + j0);
            float2 ho;
#pragma unroll
            for (int cc = 0; cc < 2; cc++) {
                const int j = j0 + cc;
                const int ci = hm * 2 + cc;
                float gir, giz, gin;
                if constexpr (HAS_GI) {
                    gir = acc_gi[0][nh][ci] + bih[j];
                    giz = acc_gi[1][nh][ci] + bih[HDIM + j];
                    gin = acc_gi[2][nh][ci] + bih[2 * HDIM + j];
                } else {
                    gir = bih[j];
                    giz = bih[HDIM + j];
                    gin = bih[2 * HDIM + j];
                    const float* wr = WihS + j * IN_FEAT;
                    const float* wz = WihS + (HDIM + j) * IN_FEAT;
                    const float* wn_ = WihS + (2 * HDIM + j) * IN_FEAT;
#pragma unroll
                    for (int i = 0; i < IN_FEAT; i++) {
                        gir += xv[i] * wr[i];
                        giz += xv[i] * wz[i];
                        gin += xv[i] * wn_[i];
                    }
                }
                float ghr = acc_gh[0][nh][ci] + bhh[j];
                float ghz = acc_gh[1][nh][ci] + bhh[HDIM + j];
                float ghn = acc_gh[2][nh][ci] + bhh[2 * HDIM + j];
                float rg = sigmoidf_(gir + ghr);
                float zg = sigmoidf_(giz + ghz);
                float ng = tanhf(gin + rg * ghn);
                float hpv = cc ? hp.y : hp.x;
                float hv = (1.0f - zg) * ng + zg * hpv;
                if (cc) ho.y = hv; else ho.x = hv;
            }
            *(float2*)(hout + row * HDIM + j0) = ho;
            __half2 h2;
            h2.x = __float2half(ho.x);
            h2.y = __float2half(ho.y);
            *(__half2*)(hout16 + row * HDIM + j0) = h2;
        }
    }
}

#define ENC_BSTRIDE (320 * 72)
#define DEC_BSTRIDE (160 * 72)
#define ENC_SMEM    (2 * ENC_BSTRIDE * 2)   // 92160 bytes
#define DEC_SMEM    (2 * DEC_BSTRIDE * 2)   // 46080 bytes

// ---------------------------------------------------------------------------
// Fused encoder step: blocks [0,128) -> layer0 h0[t]; [128,256) -> layer1
// h1[t-1] (one-step lag makes the two halves independent).
// ---------------------------------------------------------------------------
__global__ __launch_bounds__(256, 2)
void enc_step_kernel(int t, const float* __restrict__ src,
                     const float* __restrict__ bih0, const float* __restrict__ bhh0,
                     const float* __restrict__ Wih0,
                     const float* __restrict__ bih1, const float* __restrict__ bhh1) {
    extern __shared__ __align__(16) __half dynsmem[];
    const int role = (blockIdx.x < 128) ? 0 : 1;
    const int bid = blockIdx.x & 127;
    const int m0 = (bid >> 4) * 64;
    const int n0 = (bid & 15) * 32;

    if (role == 0) {
        if (t >= TSTEPS) return;
        const int pw = t & 1, pr = (t + 1) & 1;   // h0[t-1] at parity (t-1)&1
        gru_block<false, 8, false, ENC_BSTRIDE>(dynsmem, m0, n0,
            g_h0_f16[pr], g_Whh0, nullptr, nullptr,
            bih0, bhh0, Wih0, src + t * 8, TSTEPS * 8, nullptr,
            g_h0_f32[pr], g_h0_f32[pw], g_h0_f16[pw]);
    } else {
        if (t < 1) return;
        const int tt = t - 1;                     // computing h1[tt]
        const int pw = tt & 1, pr = (tt + 1) & 1; // h1[tt-1] parity
        gru_block<true, 0, false, ENC_BSTRIDE>(dynsmem, m0, n0,
            g_h1_f16[pr], g_Whh1, g_h0_f16[tt & 1], g_Wih1,
            bih1, bhh1, nullptr, nullptr, 0, nullptr,
            g_h1_f32[pr], g_h1_f32[pw], g_h1_f16[pw]);
    }
}

// ---------------------------------------------------------------------------
// Decoder GRU cell step (gi inline from [last_value, tf_t], 9 features)
// ---------------------------------------------------------------------------
__global__ __launch_bounds__(256, 2)
void dec_step_kernel(int s, const float* __restrict__ tf,
                     const float* __restrict__ cbih, const float* __restrict__ cbhh,
                     const float* __restrict__ cWih) {
    extern __shared__ __align__(16) __half dynsmem[];
    const int bid = blockIdx.x;
    const int m0 = (bid >> 4) * 64;
    const int n0 = (bid & 15) * 32;
    const int pr = s & 1, pw = (s + 1) & 1;
    gru_block<false, 9, true, DEC_BSTRIDE>(dynsmem, m0, n0,
        g_hd_f16[pr], g_cWhh, nullptr, nullptr,
        cbih, cbhh, cWih, tf + s * 8, HORIZON * 8, g_lastv,
        g_hd_f32[pr], g_hd_f32[pw], g_hd_f16[pw]);
}

// ---------------------------------------------------------------------------
// fc head: pred[b] = hidden[b] . fc_W + fc_b ; also feeds next last_value
// ---------------------------------------------------------------------------
__global__ __launch_bounds__(256)
void fc_kernel(int s, const float* __restrict__ fcW, const float* __restrict__ fcb,
               float* __restrict__ out) {
    const int b = blockIdx.x * 8 + (threadIdx.x >> 5);
    const int lane = threadIdx.x & 31;
    const float* h = g_hd_f32[(s + 1) & 1] + b * HDIM;
    float sum = 0.f;
#pragma unroll
    for (int k = lane; k < HDIM; k += 32) sum += h[k] * fcW[k];
#pragma unroll
    for (int o = 16; o; o >>= 1) sum += __shfl_xor_sync(0xffffffffu, sum, o);
    if (lane == 0) {
        float p = sum + fcb[0];
        out[b * HORIZON + s] = p;
        g_lastv[b] = p;
    }
}

// ---------------------------------------------------------------------------
// dec0 linear: hidden0 = h1[T-1] @ dec0_Wᵀ + dec0_b  (one-time, fp32 SIMT)
// ---------------------------------------------------------------------------
__global__ __launch_bounds__(256)
void dec0_kernel(const float* __restrict__ W, const float* __restrict__ bias) {
    __shared__ float As[64][17];
    __shared__ float Ws[64][17];
    const float* A = g_h1_f32[(TSTEPS - 1) & 1];
    const int m0 = blockIdx.y * 64, n0 = blockIdx.x * 64;
    const int tx = threadIdx.x & 15, ty = threadIdx.x >> 4;
    float acc[4][4] = {};
    for (int k0 = 0; k0 < HDIM; k0 += 16) {
#pragma unroll
        for (int i = 0; i < 4; i++) {
            int idx = threadIdx.x + i * 256;
            int r = idx >> 4, c = idx & 15;
            As[r][c] = A[(m0 + r) * HDIM + k0 + c];
            Ws[r][c] = W[(n0 + r) * HDIM + k0 + c];
        }
        __syncthreads();
#pragma unroll
        for (int kk = 0; kk < 16; kk++) {
            float a[4], w[4];
#pragma unroll
            for (int i = 0; i < 4; i++) { a[i] = As[ty * 4 + i][kk]; w[i] = Ws[tx * 4 + i][kk]; }
#pragma unroll
            for (int i = 0; i < 4; i++)
#pragma unroll
                for (int j = 0; j < 4; j++) acc[i][j] += a[i] * w[j];
        }
        __syncthreads();
    }
#pragma unroll
    for (int i = 0; i < 4; i++)
#pragma unroll
        for (int j = 0; j < 4; j++) {
            int m = m0 + ty * 4 + i, n = n0 + tx * 4 + j;
            float v = acc[i][j] + bias[n];
            g_hd_f32[0][m * HDIM + n] = v;
            g_hd_f16[0][m * HDIM + n] = __float2half(v);
        }
}

// ---------------------------------------------------------------------------
// setup kernels
// ---------------------------------------------------------------------------
__global__ void convert_weights_kernel(const float* __restrict__ Whh0,
                                       const float* __restrict__ Wih1,
                                       const float* __restrict__ Whh1,
                                       const float* __restrict__ cWhh) {
    int i = blockIdx.x * blockDim.x + threadIdx.x;
    if (i < G3H * HDIM) {
        g_Whh0[i] = __float2half(Whh0[i]);
        g_Wih1[i] = __float2half(Wih1[i]);
        g_Whh1[i] = __float2half(Whh1[i]);
        g_cWhh[i] = __float2half(cWhh[i]);
    }
}

__global__ void init_kernel(const float* __restrict__ src) {
    int i = blockIdx.x * blockDim.x + threadIdx.x;
    if (i < BATCH * HDIM) {
        g_h0_f32[1][i] = 0.f;
        g_h1_f32[1][i] = 0.f;
        g_h0_f16[1][i] = __float2half(0.f);
        g_h1_f16[1][i] = __float2half(0.f);
    }
    if (i < BATCH) g_lastv[i] = src[i * (TSTEPS * 8) + (TSTEPS - 1) * 8];
}

// ---------------------------------------------------------------------------
extern "C" void kernel_launch(void* const* d_in, const int* in_sizes, int n_in,
                              void* d_out, int out_size) {
    const float* src   = (const float*)d_in[0];
    const float* tf    = (const float*)d_in[1];
    const float* Wih0  = (const float*)d_in[2];
    const float* Whh0  = (const float*)d_in[3];
    const float* bih0  = (const float*)d_in[4];
    const float* bhh0  = (const float*)d_in[5];
    const float* Wih1  = (const float*)d_in[6];
    const float* Whh1  = (const float*)d_in[7];
    const float* bih1  = (const float*)d_in[8];
    const float* bhh1  = (const float*)d_in[9];
    const float* dec0W = (const float*)d_in[10];
    const float* dec0b = (const float*)d_in[11];
    const float* cWih  = (const float*)d_in[12];
    const float* cWhh  = (const float*)d_in[13];
    const float* cbih  = (const float*)d_in[14];
    const float* cbhh  = (const float*)d_in[15];
    const float* fcW   = (const float*)d_in[16];
    const float* fcb   = (const float*)d_in[17];
    float* out = (float*)d_out;

    cudaFuncSetAttribute(enc_step_kernel,
                         cudaFuncAttributeMaxDynamicSharedMemorySize, ENC_SMEM);
    cudaFuncSetAttribute(dec_step_kernel,
                         cudaFuncAttributeMaxDynamicSharedMemorySize, DEC_SMEM);

    convert_weights_kernel<<<(G3H * HDIM + 255) / 256, 256>>>(Whh0, Wih1, Whh1, cWhh);
    init_kernel<<<(BATCH * HDIM + 255) / 256, 256>>>(src);

    // Encoder: T+1 fused launches (layer1 lags layer0 by one step)
    for (int t = 0; t <= TSTEPS; t++)
        enc_step_kernel<<<256, 256, ENC_SMEM>>>(t, src, bih0, bhh0, Wih0, bih1, bhh1);

    // Decoder init + 48 steps
    dec0_kernel<<<dim3(8, 8), 256>>>(dec0W, dec0b);
    for (int s = 0; s < HORIZON; s++) {
        dec_step_kernel<<<128, 256, DEC_SMEM>>>(s, tf, cbih, cbhh, cWih);
        fc_kernel<<<64, 256>>>(s, fcW, fcb, out);
    }
}

// round 10
// speedup vs baseline: 1.3598x; 1.1017x over previous
#include <cuda_runtime.h>
#include <cuda_fp16.h>
#include <cstdint>

// ---------------------------------------------------------------------------
// Seq2SeqForecast: 2-layer GRU encoder (B=512, T=336, H=512) + 48-step GRU
// decoder with scalar head.
//
// R9 changes vs R8 (7287us, enc_step 25.5us, tensor 16.6%, L1 33%):
//  * ldmatrix.x4 fragment loads (A and B) replace scalar LDS.32 — 4x fewer
//    shared-pipe ops per MMA; layout (stride-72 halves) is LDSM-conflict-free
//    and fragment ordering matches mma, so epilogue is unchanged.
// Kept from R8: __launch_bounds__(256,2), cp.async.cg double-buffer pipeline,
// fused encoder step (layer1 lags layer0 by one step), ping-pong parity bufs.
// ---------------------------------------------------------------------------

#define HDIM   512
#define BATCH  512
#define TSTEPS 336
#define HORIZON 48
#define G3H    (3 * HDIM)          // 1536

// fp16 weight copies
__device__ __half g_Whh0[G3H * HDIM];
__device__ __half g_Wih1[G3H * HDIM];
__device__ __half g_Whh1[G3H * HDIM];
__device__ __half g_cWhh[G3H * HDIM];

// hidden-state ping-pong buffers (fp32 master + fp16 shadow for MMA)
__device__ float  g_h0_f32[2][BATCH * HDIM];
__device__ __half g_h0_f16[2][BATCH * HDIM];
__device__ float  g_h1_f32[2][BATCH * HDIM];
__device__ __half g_h1_f16[2][BATCH * HDIM];
__device__ float  g_hd_f32[2][BATCH * HDIM];
__device__ __half g_hd_f16[2][BATCH * HDIM];
__device__ float  g_lastv[BATCH];

// ---------------------------------------------------------------------------
// helpers
// ---------------------------------------------------------------------------
__device__ __forceinline__ void mma16816(float (&c)[4], const uint32_t (&a)[4],
                                         uint32_t b0, uint32_t b1) {
    asm volatile(
        "mma.sync.aligned.m16n8k16.row.col.f32.f16.f16.f32 "
        "{%0,%1,%2,%3}, {%4,%5,%6,%7}, {%8,%9}, {%0,%1,%2,%3};\n"
        : "+f"(c[0]), "+f"(c[1]), "+f"(c[2]), "+f"(c[3])
        : "r"(a[0]), "r"(a[1]), "r"(a[2]), "r"(a[3]), "r"(b0), "r"(b1));
}

__device__ __forceinline__ void ldsm4(uint32_t (&r)[4], uint32_t saddr) {
    asm volatile(
        "ldmatrix.sync.aligned.m8n8.x4.shared.b16 {%0,%1,%2,%3}, [%4];\n"
        : "=r"(r[0]), "=r"(r[1]), "=r"(r[2]), "=r"(r[3]) : "r"(saddr));
}

__device__ __forceinline__ float sigmoidf_(float x) {
    return 1.0f / (1.0f + expf(-x));
}

__device__ __forceinline__ void cp16(uint32_t dst, const void* src) {
    asm volatile("cp.async.cg.shared.global [%0], [%1], 16;\n"
                 :: "r"(dst), "l"(src));
}
__device__ __forceinline__ void cp_commit() {
    asm volatile("cp.async.commit_group;\n");
}
template <int N>
__device__ __forceinline__ void cp_wait() {
    asm volatile("cp.async.wait_group %0;\n" :: "n"(N));
}

// ---------------------------------------------------------------------------
// Core GRU tile: block computes a 64(batch) x 32(hidden) tile of h_new.
// gh = h_prev @ Wghᵀ (+bhh) always via MMA.
// gi either via MMA (HAS_GI: layer1) or inline small dot (IN_FEAT = 8 or 9).
// Double-buffered smem (stride BSTRIDE halves per buffer); per-buffer layout
// (row stride 72 halves): As0[64] Bs0[96] [As1[64] Bs1[96] if HAS_GI].
// ---------------------------------------------------------------------------
template <bool HAS_GI, int IN_FEAT, bool HAS_XFIRST, int BSTRIDE>
__device__ __forceinline__ void gru_block(
    __half* __restrict__ smem, int m0, int n0,
    const __half* __restrict__ Agh, const __half* __restrict__ Wgh,
    const __half* __restrict__ Agi, const __half* __restrict__ Wgi,
    const float* __restrict__ bih, const float* __restrict__ bhh,
    const float* __restrict__ WihS,  // [1536 x IN_FEAT] small input weights
    const float* __restrict__ xrow, int xstride,
    const float* __restrict__ xfirst,
    const float* __restrict__ hprev, float* __restrict__ hout,
    __half* __restrict__ hout16) {

    const int tid  = threadIdx.x;
    const int lane = tid & 31;
    const int wid  = tid >> 5;       // 8 warps
    const int wm   = wid >> 1;       // 4 warps along M
    const int wn   = wid & 1;        // 2 warps along N
    const int g4   = lane >> 2;      // 0..7
    const int t4   = lane & 3;       // 0..3

    // ---- cp.async staging setup ----
    const int r8 = tid >> 3;         // 0..31
    const int c8 = tid & 7;          // 0..7 (uint4 within 64-half k-chunk)
    const uint32_t sbase = (uint32_t)__cvta_generic_to_shared(smem);
    const uint32_t sA  = sbase + (uint32_t)((r8 * 72 + c8 * 8) * 2);
    const uint32_t sB  = sbase + (uint32_t)((64 * 72 + r8 * 72 + c8 * 8) * 2);
    const __half* pA0   = Agh + (m0 + r8) * HDIM + c8 * 8;
    const __half* pB0_0 = Wgh + (0 * HDIM + n0 + r8) * HDIM + c8 * 8;
    const __half* pB0_1 = Wgh + (1 * HDIM + n0 + r8) * HDIM + c8 * 8;
    const __half* pB0_2 = Wgh + (2 * HDIM + n0 + r8) * HDIM + c8 * 8;
    const __half* pA1   = HAS_GI ? Agi + (m0 + r8) * HDIM + c8 * 8 : nullptr;
    const __half* pB1_0 = HAS_GI ? Wgi + (0 * HDIM + n0 + r8) * HDIM + c8 * 8 : nullptr;
    const __half* pB1_1 = HAS_GI ? Wgi + (1 * HDIM + n0 + r8) * HDIM + c8 * 8 : nullptr;
    const __half* pB1_2 = HAS_GI ? Wgi + (2 * HDIM + n0 + r8) * HDIM + c8 * 8 : nullptr;

    auto stage = [&](int ks) {
        const uint32_t bo = (uint32_t)((ks & 1) * BSTRIDE * 2);
        const int ko = ks * 64;
        cp16(sA + bo, pA0 + ko);
        cp16(sA + bo + 32 * 72 * 2, pA0 + 32 * HDIM + ko);
        cp16(sB + bo, pB0_0 + ko);
        cp16(sB + bo + 32 * 72 * 2, pB0_1 + ko);
        cp16(sB + bo + 64 * 72 * 2, pB0_2 + ko);
        if (HAS_GI) {
            const uint32_t bo1 = bo + 160 * 72 * 2;
            cp16(sA + bo1, pA1 + ko);
            cp16(sA + bo1 + 32 * 72 * 2, pA1 + 32 * HDIM + ko);
            cp16(sB + bo1, pB1_0 + ko);
            cp16(sB + bo1 + 32 * 72 * 2, pB1_1 + ko);
            cp16(sB + bo1 + 64 * 72 * 2, pB1_2 + ko);
        }
        cp_commit();
    };

    float acc_gh[3][2][4];
    float acc_gi[3][2][4];
#pragma unroll
    for (int g = 0; g < 3; g++)
#pragma unroll
        for (int nh = 0; nh < 2; nh++)
#pragma unroll
            for (int i = 0; i < 4; i++) {
                acc_gh[g][nh][i] = 0.f;
                if (HAS_GI) acc_gi[g][nh][i] = 0.f;
            }

    // ---- ldmatrix per-lane addressing ----
    // x4 tile order: lanes[0:8)=rows 0-7/k0, [8:16)=rows 8-15/k0,
    //                [16:24)=rows 0-7/k8, [24:32)=rows 8-15/k8
    // => row = lane&15, k-chunk(8) = lane>>4. Matches mma A/B fragments.
    const int lane15 = lane & 15;
    const int lhi8   = (lane >> 4) * 8;
    const uint32_t aoff = (uint32_t)(((wm * 16 + lane15) * 72 + lhi8) * 2);
    uint32_t boff[3];
#pragma unroll
    for (int g = 0; g < 3; g++)
        boff[g] = (uint32_t)(((64 + g * 32 + wn * 16 + lane15) * 72 + lhi8) * 2);
    const uint32_t GIOFF = (uint32_t)(160 * 72 * 2);

    stage(0);

    for (int ks = 0; ks < 8; ks++) {
        if (ks < 7) { stage(ks + 1); cp_wait<1>(); }
        else        { cp_wait<0>(); }
        __syncthreads();

        const uint32_t base = sbase + (uint32_t)((ks & 1) * BSTRIDE * 2);

#pragma unroll
        for (int kk = 0; kk < 64; kk += 16) {
            uint32_t a0[4], a1[4];
            ldsm4(a0, base + aoff + kk * 2);
            if (HAS_GI) ldsm4(a1, base + GIOFF + aoff + kk * 2);
#pragma unroll
            for (int g = 0; g < 3; g++) {
                uint32_t b[4];
                ldsm4(b, base + boff[g] + kk * 2);
                mma16816(acc_gh[g][0], a0, b[0], b[2]);
                mma16816(acc_gh[g][1], a0, b[1], b[3]);
                if (HAS_GI) {
                    uint32_t c[4];
                    ldsm4(c, base + GIOFF + boff[g] + kk * 2);
                    mma16816(acc_gi[g][0], a1, c[0], c[2]);
                    mma16816(acc_gi[g][1], a1, c[1], c[3]);
                }
            }
        }
        __syncthreads();
    }

    // ---- epilogue: gates fully in registers (known mma C layout) ----
    const int mbase = m0 + wm * 16 + g4;
    const int nbase = n0 + wn * 16 + t4 * 2;

#pragma unroll
    for (int hm = 0; hm < 2; hm++) {
        const int row = mbase + hm * 8;
        float xv[IN_FEAT > 0 ? IN_FEAT : 1];
        if constexpr (!HAS_GI) {
            if constexpr (HAS_XFIRST) {
                xv[0] = xfirst[row];
#pragma unroll
                for (int i = 1; i < IN_FEAT; i++)
                    xv[i] = xrow[row * xstride + i - 1];
            } else {
#pragma unroll
                for (int i = 0; i < IN_FEAT; i++)
                    xv[i] = xrow[row * xstride + i];
            }
        }
#pragma unroll
        for (int nh = 0; nh < 2; nh++) {
            const int j0 = nbase + nh * 8;
            float2 hp = *(const float2*)(hprev + row * HDIM + j0);
            float2 ho;
#pragma unroll
            for (int cc = 0; cc < 2; cc++) {
                const int j = j0 + cc;
                const int ci = hm * 2 + cc;
                float gir, giz, gin;
                if constexpr (HAS_GI) {
                    gir = acc_gi[0][nh][ci] + bih[j];
                    giz = acc_gi[1][nh][ci] + bih[HDIM + j];
                    gin = acc_gi[2][nh][ci] + bih[2 * HDIM + j];
                } else {
                    gir = bih[j];
                    giz = bih[HDIM + j];
                    gin = bih[2 * HDIM + j];
                    const float* wr = WihS + j * IN_FEAT;
                    const float* wz = WihS + (HDIM + j) * IN_FEAT;
                    const float* wn_ = WihS + (2 * HDIM + j) * IN_FEAT;
#pragma unroll
                    for (int i = 0; i < IN_FEAT; i++) {
                        gir += xv[i] * wr[i];
                        giz += xv[i] * wz[i];
                        gin += xv[i] * wn_[i];
                    }
                }
                float ghr = acc_gh[0][nh][ci] + bhh[j];
                float ghz = acc_gh[1][nh][ci] + bhh[HDIM + j];
                float ghn = acc_gh[2][nh][ci] + bhh[2 * HDIM + j];
                float rg = sigmoidf_(gir + ghr);
                float zg = sigmoidf_(giz + ghz);
                float ng = tanhf(gin + rg * ghn);
                float hpv = cc ? hp.y : hp.x;
                float hv = (1.0f - zg) * ng + zg * hpv;
                if (cc) ho.y = hv; else ho.x = hv;
            }
            *(float2*)(hout + row * HDIM + j0) = ho;
            __half2 h2;
            h2.x = __float2half(ho.x);
            h2.y = __float2half(ho.y);
            *(__half2*)(hout16 + row * HDIM + j0) = h2;
        }
    }
}

#define ENC_BSTRIDE (320 * 72)
#define DEC_BSTRIDE (160 * 72)
#define ENC_SMEM    (2 * ENC_BSTRIDE * 2)   // 92160 bytes
#define DEC_SMEM    (2 * DEC_BSTRIDE * 2)   // 46080 bytes

// ---------------------------------------------------------------------------
// Fused encoder step: blocks [0,128) -> layer0 h0[t]; [128,256) -> layer1
// h1[t-1] (one-step lag makes the two halves independent).
// ---------------------------------------------------------------------------
__global__ __launch_bounds__(256, 2)
void enc_step_kernel(int t, const float* __restrict__ src,
                     const float* __restrict__ bih0, const float* __restrict__ bhh0,
                     const float* __restrict__ Wih0,
                     const float* __restrict__ bih1, const float* __restrict__ bhh1) {
    extern __shared__ __align__(16) __half dynsmem[];
    const int role = (blockIdx.x < 128) ? 0 : 1;
    const int bid = blockIdx.x & 127;
    const int m0 = (bid >> 4) * 64;
    const int n0 = (bid & 15) * 32;

    if (role == 0) {
        if (t >= TSTEPS) return;
        const int pw = t & 1, pr = (t + 1) & 1;   // h0[t-1] at parity (t-1)&1
        gru_block<false, 8, false, ENC_BSTRIDE>(dynsmem, m0, n0,
            g_h0_f16[pr], g_Whh0, nullptr, nullptr,
            bih0, bhh0, Wih0, src + t * 8, TSTEPS * 8, nullptr,
            g_h0_f32[pr], g_h0_f32[pw], g_h0_f16[pw]);
    } else {
        if (t < 1) return;
        const int tt = t - 1;                     // computing h1[tt]
        const int pw = tt & 1, pr = (tt + 1) & 1; // h1[tt-1] parity
        gru_block<true, 0, false, ENC_BSTRIDE>(dynsmem, m0, n0,
            g_h1_f16[pr], g_Whh1, g_h0_f16[tt & 1], g_Wih1,
            bih1, bhh1, nullptr, nullptr, 0, nullptr,
            g_h1_f32[pr], g_h1_f32[pw], g_h1_f16[pw]);
    }
}

// ---------------------------------------------------------------------------
// Decoder GRU cell step (gi inline from [last_value, tf_t], 9 features)
// ---------------------------------------------------------------------------
__global__ __launch_bounds__(256, 2)
void dec_step_kernel(int s, const float* __restrict__ tf,
                     const float* __restrict__ cbih, const float* __restrict__ cbhh,
                     const float* __restrict__ cWih) {
    extern __shared__ __align__(16) __half dynsmem[];
    const int bid = blockIdx.x;
    const int m0 = (bid >> 4) * 64;
    const int n0 = (bid & 15) * 32;
    const int pr = s & 1, pw = (s + 1) & 1;
    gru_block<false, 9, true, DEC_BSTRIDE>(dynsmem, m0, n0,
        g_hd_f16[pr], g_cWhh, nullptr, nullptr,
        cbih, cbhh, cWih, tf + s * 8, HORIZON * 8, g_lastv,
        g_hd_f32[pr], g_hd_f32[pw], g_hd_f16[pw]);
}

// ---------------------------------------------------------------------------
// fc head: pred[b] = hidden[b] . fc_W + fc_b ; also feeds next last_value
// ---------------------------------------------------------------------------
__global__ __launch_bounds__(256)
void fc_kernel(int s, const float* __restrict__ fcW, const float* __restrict__ fcb,
               float* __restrict__ out) {
    const int b = blockIdx.x * 8 + (threadIdx.x >> 5);
    const int lane = threadIdx.x & 31;
    const float* h = g_hd_f32[(s + 1) & 1] + b * HDIM;
    float sum = 0.f;
#pragma unroll
    for (int k = lane; k < HDIM; k += 32) sum += h[k] * fcW[k];
#pragma unroll
    for (int o = 16; o; o >>= 1) sum += __shfl_xor_sync(0xffffffffu, sum, o);
    if (lane == 0) {
        float p = sum + fcb[0];
        out[b * HORIZON + s] = p;
        g_lastv[b] = p;
    }
}

// ---------------------------------------------------------------------------
// dec0 linear: hidden0 = h1[T-1] @ dec0_Wᵀ + dec0_b  (one-time, fp32 SIMT)
// ---------------------------------------------------------------------------
__global__ __launch_bounds__(256)
void dec0_kernel(const float* __restrict__ W, const float* __restrict__ bias) {
    __shared__ float As[64][17];
    __shared__ float Ws[64][17];
    const float* A = g_h1_f32[(TSTEPS - 1) & 1];
    const int m0 = blockIdx.y * 64, n0 = blockIdx.x * 64;
    const int tx = threadIdx.x & 15, ty = threadIdx.x >> 4;
    float acc[4][4] = {};
    for (int k0 = 0; k0 < HDIM; k0 += 16) {
#pragma unroll
        for (int i = 0; i < 4; i++) {
            int idx = threadIdx.x + i * 256;
            int r = idx >> 4, c = idx & 15;
            As[r][c] = A[(m0 + r) * HDIM + k0 + c];
            Ws[r][c] = W[(n0 + r) * HDIM + k0 + c];
        }
        __syncthreads();
#pragma unroll
        for (int kk = 0; kk < 16; kk++) {
            float a[4], w[4];
#pragma unroll
            for (int i = 0; i < 4; i++) { a[i] = As[ty * 4 + i][kk]; w[i] = Ws[tx * 4 + i][kk]; }
#pragma unroll
            for (int i = 0; i < 4; i++)
#pragma unroll
                for (int j = 0; j < 4; j++) acc[i][j] += a[i] * w[j];
        }
        __syncthreads();
    }
#pragma unroll
    for (int i = 0; i < 4; i++)
#pragma unroll
        for (int j = 0; j < 4; j++) {
            int m = m0 + ty * 4 + i, n = n0 + tx * 4 + j;
            float v = acc[i][j] + bias[n];
            g_hd_f32[0][m * HDIM + n] = v;
            g_hd_f16[0][m * HDIM + n] = __float2half(v);
        }
}

// ---------------------------------------------------------------------------
// setup kernels
// ---------------------------------------------------------------------------
__global__ void convert_weights_kernel(const float* __restrict__ Whh0,
                                       const float* __restrict__ Wih1,
                                       const float* __restrict__ Whh1,
                                       const float* __restrict__ cWhh) {
    int i = blockIdx.x * blockDim.x + threadIdx.x;
    if (i < G3H * HDIM) {
        g_Whh0[i] = __float2half(Whh0[i]);
        g_Wih1[i] = __float2half(Wih1[i]);
        g_Whh1[i] = __float2half(Whh1[i]);
        g_cWhh[i] = __float2half(cWhh[i]);
    }
}

__global__ void init_kernel(const float* __restrict__ src) {
    int i = blockIdx.x * blockDim.x + threadIdx.x;
    if (i < BATCH * HDIM) {
        g_h0_f32[1][i] = 0.f;
        g_h1_f32[1][i] = 0.f;
        g_h0_f16[1][i] = __float2half(0.f);
        g_h1_f16[1][i] = __float2half(0.f);
    }
    if (i < BATCH) g_lastv[i] = src[i * (TSTEPS * 8) + (TSTEPS - 1) * 8];
}

// ---------------------------------------------------------------------------
extern "C" void kernel_launch(void* const* d_in, const int* in_sizes, int n_in,
                              void* d_out, int out_size) {
    const float* src   = (const float*)d_in[0];
    const float* tf    = (const float*)d_in[1];
    const float* Wih0  = (const float*)d_in[2];
    const float* Whh0  = (const float*)d_in[3];
    const float* bih0  = (const float*)d_in[4];
    const float* bhh0  = (const float*)d_in[5];
    const float* Wih1  = (const float*)d_in[6];
    const float* Whh1  = (const float*)d_in[7];
    const float* bih1  = (const float*)d_in[8];
    const float* bhh1  = (const float*)d_in[9];
    const float* dec0W = (const float*)d_in[10];
    const float* dec0b = (const float*)d_in[11];
    const float* cWih  = (const float*)d_in[12];
    const float* cWhh  = (const float*)d_in[13];
    const float* cbih  = (const float*)d_in[14];
    const float* cbhh  = (const float*)d_in[15];
    const float* fcW   = (const float*)d_in[16];
    const float* fcb   = (const float*)d_in[17];
    float* out = (float*)d_out;

    cudaFuncSetAttribute(enc_step_kernel,
                         cudaFuncAttributeMaxDynamicSharedMemorySize, ENC_SMEM);
    cudaFuncSetAttribute(dec_step_kernel,
                         cudaFuncAttributeMaxDynamicSharedMemorySize, DEC_SMEM);

    convert_weights_kernel<<<(G3H * HDIM + 255) / 256, 256>>>(Whh0, Wih1, Whh1, cWhh);
    init_kernel<<<(BATCH * HDIM + 255) / 256, 256>>>(src);

    // Encoder: T+1 fused launches (layer1 lags layer0 by one step)
    for (int t = 0; t <= TSTEPS; t++)
        enc_step_kernel<<<256, 256, ENC_SMEM>>>(t, src, bih0, bhh0, Wih0, bih1, bhh1);

    // Decoder init + 48 steps
    dec0_kernel<<<dim3(8, 8), 256>>>(dec0W, dec0b);
    for (int s = 0; s < HORIZON; s++) {
        dec_step_kernel<<<128, 256, DEC_SMEM>>>(s, tf, cbih, cbhh, cWih);
        fc_kernel<<<64, 256>>>(s, fcW, fcb, out);
    }
}